// round 11
// baseline (speedup 1.0000x reference)
#include <cuda_runtime.h>
#include <cuda.h>
#include <cstdint>

#define N_ATOMS_MAX 2000000
#define N_MOL_MAX   50000

#define K_DIM   128
#define N_DIM   64
#define TILE_M  128
#define GRID_P  304          // 2 blocks per SM on 152-SM GB300
#define NSTAGES 4
#define CHUNK_BYTES  16384   // 128 rows x 32 f32 (128B/row, SW128)
#define NTHREADS 288         // 8 consumer warps + 1 producer warp

// smem float offsets
#define BF_OFF     16384     // after 4 x 4096-float X stages
#define B1_OFF     26624     // Bf = 10240 u32 (40 KB, stride-20 conflict-free)
#define W2_OFF     26688
#define FULL_OFF   26752     // 4 x u64
#define EMPTY_OFF  26760     // 4 x u64
#define SMEM_FLOATS 26768

// scratch (no device allocation allowed)
__device__ float g_atom_out[N_ATOMS_MAX];
__device__ int   g_start[N_MOL_MAX + 1];

__device__ __forceinline__ uint32_t f2tf32(float f) {
    uint32_t u;
    asm("cvt.rna.tf32.f32 %0, %1;" : "=r"(u) : "f"(f));
    return u;
}
__device__ __forceinline__ float silu(float v) {
    return __fdividef(v, 1.0f + __expf(-v));
}
__device__ __forceinline__ void mbar_init(uint32_t mb, uint32_t cnt) {
    asm volatile("mbarrier.init.shared.b64 [%0], %1;" :: "r"(mb), "r"(cnt) : "memory");
}
__device__ __forceinline__ void mbar_wait(uint32_t mb, uint32_t phase) {
    asm volatile(
        "{\n\t.reg .pred P;\n"
        "W%=:\n\t"
        "mbarrier.try_wait.parity.acquire.cta.shared::cta.b64 P, [%0], %1, 0x989680;\n\t"
        "@P bra D%=;\n\t"
        "bra W%=;\n"
        "D%=:\n\t}"
        :: "r"(mb), "r"(phase) : "memory");
}
__device__ __forceinline__ void mbar_arrive(uint32_t mb) {
    asm volatile("mbarrier.arrive.shared.b64 _, [%0];" :: "r"(mb) : "memory");
}
#define MMA_TF32(C, A0, A1, A2, A3, B0, B1)                                   \
    asm("mma.sync.aligned.m16n8k8.row.col.f32.tf32.tf32.f32 "                 \
        "{%0,%1,%2,%3}, {%4,%5,%6,%7}, {%8,%9}, {%0,%1,%2,%3};"               \
        : "+f"(C[0]), "+f"(C[1]), "+f"(C[2]), "+f"(C[3])                      \
        : "r"(A0), "r"(A1), "r"(A2), "r"(A3), "r"(B0), "r"(B1))

// ---------------------------------------------------------------------------
// Kernel 1: persistent per-atom MLP, TMA-fed 4-deep ring, warp-specialized.
// 8 consumer warps x 16 rows; tiles processed in PAIRS so each B fragment
// load serves two tiles (B LDS per row equal to the 32-row layout, but with
// twice the warps for latency hiding). Warp 8 is the sole TMA producer.
// Chunk cn: pair p = cn>>3, q = (cn>>1)&3, sub = cn&1;
//   global tile = 2*(blockIdx + p*GRID_P) + sub (phantom tile -> TMA OOB zero).
// ---------------------------------------------------------------------------
__global__ __launch_bounds__(NTHREADS, 2)
void mlp_kernel(const __grid_constant__ CUtensorMap tmap,
                const float* __restrict__ W1,
                const float* __restrict__ b1,
                const float* __restrict__ W2,
                const float* __restrict__ b2,
                int n_atoms, int npairs)
{
    extern __shared__ __align__(1024) float smem[];
    uint32_t* Bf  = (uint32_t*)(smem + BF_OFF);
    float*    b1s = smem + B1_OFF;
    float*    w2s = smem + W2_OFF;
    const uint32_t smem_base  = (uint32_t)__cvta_generic_to_shared(smem);
    const uint32_t full_base  = smem_base + FULL_OFF * 4u;
    const uint32_t empty_base = smem_base + EMPTY_OFF * 4u;
    const uint64_t tmap_ptr   = (uint64_t)&tmap;

    const int tid  = threadIdx.x;
    const int lane = tid & 31, warp = tid >> 5;
    const int g = lane >> 2, tq = lane & 3;

    // ---- stage W1 once: tf32, fragment-major, lane stride 20 (conflict-free) ----
    for (int e = tid; e < K_DIM * N_DIM; e += NTHREADS) {
        int k = e >> 6, n = e & 63;
        uint32_t v = f2tf32(W1[e]);
        int gg = n & 7, nt = n >> 3, kk = k >> 3, kb = k & 7;
        int tq2 = kb & 3, j = nt * 2 + (kb >> 2);
        Bf[kk * 640 + (gg * 4 + tq2) * 20 + j] = v;
    }
    if (tid < N_DIM) { b1s[tid] = b1[tid]; w2s[tid] = W2[tid]; }
    const float b2v = b2[0];

    const int nlocp = (blockIdx.x < npairs) ? (npairs - blockIdx.x + GRID_P - 1) / GRID_P : 0;
    const int C = nlocp * 8;                 // chunks: (pair, q, sub)

    if (tid == 0) {
        #pragma unroll
        for (int s = 0; s < NSTAGES; s++) {
            mbar_init(full_base  + s * 8, 1);
            mbar_init(empty_base + s * 8, 8);
        }
        asm volatile("fence.proxy.async.shared::cta;" ::: "memory");
    }
    __syncthreads();
    if (C <= 0) return;

    // ======================= producer warp =======================
    if (warp == 8) {
        if (lane == 0) {
            for (int cn = 0; cn < C; cn++) {
                int slot = cn & (NSTAGES - 1);
                if (cn >= NSTAGES)                  // wait slot consumed
                    mbar_wait(empty_base + slot * 8, ((cn >> 2) + 1) & 1);
                uint32_t mb  = full_base + slot * 8;
                uint32_t dst = smem_base + (uint32_t)slot * CHUNK_BYTES;
                long pr   = (long)blockIdx.x + (long)(cn >> 3) * GRID_P;
                long tile = pr * 2 + (cn & 1);
                int y = (int)(tile * TILE_M);       // may be OOB for phantom tile
                int x = ((cn >> 1) & 3) * 32;
                asm volatile("mbarrier.arrive.expect_tx.shared.b64 _, [%0], %1;"
                             :: "r"(mb), "n"(CHUNK_BYTES) : "memory");
                asm volatile("cp.async.bulk.tensor.2d.shared::cta.global.tile.mbarrier::complete_tx::bytes "
                             "[%0], [%1, {%2, %3}], [%4];"
                             :: "r"(dst), "l"(tmap_ptr), "r"(x), "r"(y), "r"(mb) : "memory");
            }
        }
        return;
    }

    // ======================= consumer warps ======================
    const int r0 = warp * 16;
    const int rowA = r0 + g;                           // rows rowA, rowA+8
    const uint32_t xm = (uint32_t)((g & 7) << 4);      // SW128 XOR mask (rows differ by 8)
    const char* smem_c = (const char*)smem;
    const uint32_t* blane = Bf + lane * 20;

    float acc0[8][4], acc1[8][4];                      // tile0 / tile1 of the pair
    const int S = C >> 1;                              // pair-q steps

    for (int s = 0; s < S; s++) {
        const int c0 = s * 2, c1 = c0 + 1;
        const int slot0 = c0 & (NSTAGES - 1);
        const int slot1 = c1 & (NSTAGES - 1);
        mbar_wait(full_base + slot0 * 8, (c0 >> 2) & 1);
        mbar_wait(full_base + slot1 * 8, (c1 >> 2) & 1);

        const char* sb0 = smem_c + slot0 * CHUNK_BYTES;
        const char* sb1 = smem_c + slot1 * CHUNK_BYTES;
        const int q = s & 3;

        if (q == 0) {
            #pragma unroll
            for (int nt = 0; nt < 8; nt++) {
                acc0[nt][0] = 0.f; acc0[nt][1] = 0.f; acc0[nt][2] = 0.f; acc0[nt][3] = 0.f;
                acc1[nt][0] = 0.f; acc1[nt][1] = 0.f; acc1[nt][2] = 0.f; acc1[nt][3] = 0.f;
            }
        }

        #pragma unroll
        for (int kkl = 0; kkl < 4; kkl++) {
            const uint32_t* bp = blane + (q * 4 + kkl) * 640;
            uint4 b01 = *(const uint4*)(bp);
            uint4 b23 = *(const uint4*)(bp + 4);
            uint4 b45 = *(const uint4*)(bp + 8);
            uint4 b67 = *(const uint4*)(bp + 12);

            uint32_t cb = (uint32_t)((kkl * 8 + tq) * 4);
            const char* p0 = sb0 + rowA * 128;
            uint32_t a0 = f2tf32(*(const float*)(p0 + (cb ^ xm)));
            uint32_t a2 = f2tf32(*(const float*)(p0 + ((cb + 16) ^ xm)));
            uint32_t a1 = f2tf32(*(const float*)(p0 + 1024 + (cb ^ xm)));
            uint32_t a3 = f2tf32(*(const float*)(p0 + 1024 + ((cb + 16) ^ xm)));
            MMA_TF32(acc0[0], a0, a1, a2, a3, b01.x, b01.y);
            MMA_TF32(acc0[1], a0, a1, a2, a3, b01.z, b01.w);
            MMA_TF32(acc0[2], a0, a1, a2, a3, b23.x, b23.y);
            MMA_TF32(acc0[3], a0, a1, a2, a3, b23.z, b23.w);
            MMA_TF32(acc0[4], a0, a1, a2, a3, b45.x, b45.y);
            MMA_TF32(acc0[5], a0, a1, a2, a3, b45.z, b45.w);
            MMA_TF32(acc0[6], a0, a1, a2, a3, b67.x, b67.y);
            MMA_TF32(acc0[7], a0, a1, a2, a3, b67.z, b67.w);

            const char* p1 = sb1 + rowA * 128;
            uint32_t c0r = f2tf32(*(const float*)(p1 + (cb ^ xm)));
            uint32_t c2r = f2tf32(*(const float*)(p1 + ((cb + 16) ^ xm)));
            uint32_t c1r = f2tf32(*(const float*)(p1 + 1024 + (cb ^ xm)));
            uint32_t c3r = f2tf32(*(const float*)(p1 + 1024 + ((cb + 16) ^ xm)));
            MMA_TF32(acc1[0], c0r, c1r, c2r, c3r, b01.x, b01.y);
            MMA_TF32(acc1[1], c0r, c1r, c2r, c3r, b01.z, b01.w);
            MMA_TF32(acc1[2], c0r, c1r, c2r, c3r, b23.x, b23.y);
            MMA_TF32(acc1[3], c0r, c1r, c2r, c3r, b23.z, b23.w);
            MMA_TF32(acc1[4], c0r, c1r, c2r, c3r, b45.x, b45.y);
            MMA_TF32(acc1[5], c0r, c1r, c2r, c3r, b45.z, b45.w);
            MMA_TF32(acc1[6], c0r, c1r, c2r, c3r, b67.x, b67.y);
            MMA_TF32(acc1[7], c0r, c1r, c2r, c3r, b67.z, b67.w);
        }

        // signal both slots consumed (one arrive per consumer warp each)
        if (lane == 0) {
            mbar_arrive(empty_base + slot0 * 8);
            mbar_arrive(empty_base + slot1 * 8);
        }

        if (q == 3) {
            long pr = (long)blockIdx.x + (long)(s >> 2) * GRID_P;
            #pragma unroll
            for (int t = 0; t < 2; t++) {
                float (*acc)[4] = t ? acc1 : acc0;
                float sA = 0.f, sB = 0.f;
                #pragma unroll
                for (int nt = 0; nt < 8; nt++) {
                    int col0 = nt * 8 + tq * 2;
                    int col1 = col0 + 1;
                    float w0 = w2s[col0], w1v = w2s[col1];
                    float bb0 = b1s[col0], bb1 = b1s[col1];
                    sA += silu(acc[nt][0] + bb0) * w0;
                    sA += silu(acc[nt][1] + bb1) * w1v;
                    sB += silu(acc[nt][2] + bb0) * w0;
                    sB += silu(acc[nt][3] + bb1) * w1v;
                }
                #pragma unroll
                for (int o = 1; o <= 2; o <<= 1) {
                    sA += __shfl_xor_sync(0xFFFFFFFFu, sA, o);
                    sB += __shfl_xor_sync(0xFFFFFFFFu, sB, o);
                }
                if (tq == 0) {
                    long rA = (pr * 2 + t) * TILE_M + r0 + g;
                    if (rA     < n_atoms) g_atom_out[rA]     = sA + b2v;
                    if (rA + 8 < n_atoms) g_atom_out[rA + 8] = sB + b2v;
                }
            }
        }
    }
}

// ---------------------------------------------------------------------------
// Kernel 2: segment boundary detection over sorted batch (coalesced).
// ---------------------------------------------------------------------------
__global__ void bounds_kernel(const int* __restrict__ batch, int n_atoms, int n_mol)
{
    int i = blockIdx.x * blockDim.x + threadIdx.x;
    if (i >= n_atoms) return;
    int b = batch[i];
    if (i == 0) {
        for (int m = 0; m <= b; m++) g_start[m] = 0;
    } else {
        int p = batch[i - 1];
        for (int m = p + 1; m <= b; m++) g_start[m] = i;
    }
    if (i == n_atoms - 1) {
        for (int m = b + 1; m <= n_mol; m++) g_start[m] = n_atoms;
    }
}

// ---------------------------------------------------------------------------
// Kernel 3: warp per molecule — coalesced segment sum, correction, writes.
// ---------------------------------------------------------------------------
__global__ void seg_out_kernel(const float* __restrict__ charge,
                               float* __restrict__ out, int n_mol)
{
    int w    = (blockIdx.x * blockDim.x + threadIdx.x) >> 5;
    int lane = threadIdx.x & 31;
    if (w >= n_mol) return;
    int s = g_start[w], e = g_start[w + 1];
    int cnt = e - s;
    if (cnt <= 0) return;
    float sum = 0.f;
    for (int i = s + lane; i < e; i += 32) sum += g_atom_out[i];
    #pragma unroll
    for (int o = 16; o; o >>= 1) sum += __shfl_xor_sync(0xFFFFFFFFu, sum, o);
    float corr = (charge[w] - sum) / (float)cnt;
    for (int i = s + lane; i < e; i += 32) out[i] = g_atom_out[i] + corr;
}

// ---------------------------------------------------------------------------
typedef CUresult (CUDAAPI *encode_fn_t)(
    CUtensorMap*, CUtensorMapDataType, cuuint32_t, void*,
    const cuuint64_t*, const cuuint64_t*, const cuuint32_t*, const cuuint32_t*,
    CUtensorMapInterleave, CUtensorMapSwizzle, CUtensorMapL2promotion,
    CUtensorMapFloatOOBfill);

extern "C" void kernel_launch(void* const* d_in, const int* in_sizes, int n_in,
                              void* d_out, int out_size)
{
    const float* x      = (const float*)d_in[0];
    const int*   batch  = (const int*)  d_in[1];
    const float* charge = (const float*)d_in[2];
    const float* W1     = (const float*)d_in[3];
    const float* b1     = (const float*)d_in[4];
    const float* W2     = (const float*)d_in[5];
    const float* b2     = (const float*)d_in[6];
    float* out = (float*)d_out;

    const int n_atoms = in_sizes[0] / K_DIM;
    const int n_mol   = in_sizes[2];
    const int ntiles  = (n_atoms + TILE_M - 1) / TILE_M;
    const int npairs  = (ntiles + 1) / 2;

    static encode_fn_t encode = nullptr;
    if (!encode) {
        void* fn = nullptr;
        cudaDriverEntryPointQueryResult qr;
        cudaGetDriverEntryPoint("cuTensorMapEncodeTiled", &fn,
                                cudaEnableDefault, &qr);
        encode = (encode_fn_t)fn;
    }

    CUtensorMap tmap;
    cuuint64_t dims[2]    = {(cuuint64_t)K_DIM, (cuuint64_t)n_atoms};
    cuuint64_t strides[1] = {(cuuint64_t)K_DIM * 4};
    cuuint32_t box[2]     = {32u, 128u};
    cuuint32_t es[2]      = {1u, 1u};
    encode(&tmap, CU_TENSOR_MAP_DATA_TYPE_FLOAT32, 2, (void*)x,
           dims, strides, box, es,
           CU_TENSOR_MAP_INTERLEAVE_NONE, CU_TENSOR_MAP_SWIZZLE_128B,
           CU_TENSOR_MAP_L2_PROMOTION_L2_128B, CU_TENSOR_MAP_FLOAT_OOB_FILL_NONE);

    const int smem_bytes = SMEM_FLOATS * 4;
    cudaFuncSetAttribute(mlp_kernel, cudaFuncAttributeMaxDynamicSharedMemorySize,
                         smem_bytes);

    mlp_kernel<<<GRID_P, NTHREADS, smem_bytes>>>(tmap, W1, b1, W2, b2, n_atoms, npairs);
    bounds_kernel<<<(n_atoms + 255) / 256, 256>>>(batch, n_atoms, n_mol);
    seg_out_kernel<<<(n_mol * 32 + 255) / 256, 256>>>(charge, out, n_mol);
}

// round 13
// speedup vs baseline: 1.0958x; 1.0958x over previous
#include <cuda_runtime.h>
#include <cuda.h>
#include <cstdint>

#define N_ATOMS_MAX 2000000
#define N_MOL_MAX   50000

#define K_DIM   128
#define N_DIM   64
#define TILE_M  128
#define GRID_P  152          // 1 persistent block per SM on 152-SM GB300
#define NSTAGES 8
#define CHUNK_BYTES  16384   // 128 rows x 32 f32 (128B/row, SW128)
#define NTHREADS 288         // 8 consumer warps + 1 producer warp

// smem float offsets
#define BF_OFF     32768     // after 8 x 4096-float X stages
#define B1_OFF     43008     // Bf = 10240 u32 (40 KB, stride-20 conflict-free)
#define W2_OFF     43072
#define FULL_OFF   43136     // 8 x u64
#define EMPTY_OFF  43152     // 8 x u64
#define SMEM_FLOATS 43168

// scratch (no device allocation allowed)
__device__ float g_atom_out[N_ATOMS_MAX];
__device__ int   g_start[N_MOL_MAX + 1];

__device__ __forceinline__ uint32_t f2tf32(float f) {
    uint32_t u;
    asm("cvt.rna.tf32.f32 %0, %1;" : "=r"(u) : "f"(f));
    return u;
}
__device__ __forceinline__ float silu(float v) {
    return __fdividef(v, 1.0f + __expf(-v));
}
__device__ __forceinline__ void mbar_init(uint32_t mb, uint32_t cnt) {
    asm volatile("mbarrier.init.shared.b64 [%0], %1;" :: "r"(mb), "r"(cnt) : "memory");
}
__device__ __forceinline__ void mbar_wait(uint32_t mb, uint32_t phase) {
    asm volatile(
        "{\n\t.reg .pred P;\n"
        "W%=:\n\t"
        "mbarrier.try_wait.parity.acquire.cta.shared::cta.b64 P, [%0], %1, 0x989680;\n\t"
        "@P bra D%=;\n\t"
        "bra W%=;\n"
        "D%=:\n\t}"
        :: "r"(mb), "r"(phase) : "memory");
}
__device__ __forceinline__ void mbar_arrive(uint32_t mb) {
    asm volatile("mbarrier.arrive.shared.b64 _, [%0];" :: "r"(mb) : "memory");
}
#define MMA_TF32(C, A0, A1, A2, A3, B0, B1)                                   \
    asm("mma.sync.aligned.m16n8k8.row.col.f32.tf32.tf32.f32 "                 \
        "{%0,%1,%2,%3}, {%4,%5,%6,%7}, {%8,%9}, {%0,%1,%2,%3};"               \
        : "+f"(C[0]), "+f"(C[1]), "+f"(C[2]), "+f"(C[3])                      \
        : "r"(A0), "r"(A1), "r"(A2), "r"(A3), "r"(B0), "r"(B1))

// ---------------------------------------------------------------------------
// Kernel 1: persistent per-atom MLP, TMA-fed 8-deep ring, warp-specialized.
// 8 consumer warps x 16 rows; tiles processed in PAIRS so each B fragment
// load serves two tiles. Warp 8 is the sole TMA producer. 1 CTA/SM so ptxas
// has the full register file (no spills).
// Chunk cn: pair p = cn>>3, q = (cn>>1)&3, sub = cn&1;
//   global tile = 2*(blockIdx + p*GRID_P) + sub (phantom tile -> TMA OOB zero).
// ---------------------------------------------------------------------------
__global__ __launch_bounds__(NTHREADS)
void mlp_kernel(const __grid_constant__ CUtensorMap tmap,
                const float* __restrict__ W1,
                const float* __restrict__ b1,
                const float* __restrict__ W2,
                const float* __restrict__ b2,
                int n_atoms, int npairs)
{
    extern __shared__ __align__(1024) float smem[];
    uint32_t* Bf  = (uint32_t*)(smem + BF_OFF);
    float*    b1s = smem + B1_OFF;
    float*    w2s = smem + W2_OFF;
    const uint32_t smem_base  = (uint32_t)__cvta_generic_to_shared(smem);
    const uint32_t full_base  = smem_base + FULL_OFF * 4u;
    const uint32_t empty_base = smem_base + EMPTY_OFF * 4u;
    const uint64_t tmap_ptr   = (uint64_t)&tmap;

    const int tid  = threadIdx.x;
    const int lane = tid & 31, warp = tid >> 5;
    const int g = lane >> 2, tq = lane & 3;

    // ---- stage W1 once: tf32, fragment-major, lane stride 20 (conflict-free) ----
    for (int e = tid; e < K_DIM * N_DIM; e += NTHREADS) {
        int k = e >> 6, n = e & 63;
        uint32_t v = f2tf32(W1[e]);
        int gg = n & 7, nt = n >> 3, kk = k >> 3, kb = k & 7;
        int tq2 = kb & 3, j = nt * 2 + (kb >> 2);
        Bf[kk * 640 + (gg * 4 + tq2) * 20 + j] = v;
    }
    if (tid < N_DIM) { b1s[tid] = b1[tid]; w2s[tid] = W2[tid]; }
    const float b2v = b2[0];

    const int nlocp = (blockIdx.x < npairs) ? (npairs - blockIdx.x + GRID_P - 1) / GRID_P : 0;
    const int C = nlocp * 8;                 // chunks: (pair, q, sub)

    if (tid == 0) {
        #pragma unroll
        for (int s = 0; s < NSTAGES; s++) {
            mbar_init(full_base  + s * 8, 1);
            mbar_init(empty_base + s * 8, 8);
        }
        asm volatile("fence.proxy.async.shared::cta;" ::: "memory");
    }
    __syncthreads();
    if (C <= 0) return;

    // ======================= producer warp =======================
    if (warp == 8) {
        if (lane == 0) {
            for (int cn = 0; cn < C; cn++) {
                int slot = cn & (NSTAGES - 1);
                if (cn >= NSTAGES)                  // wait slot consumed
                    mbar_wait(empty_base + slot * 8, ((cn >> 3) + 1) & 1);
                uint32_t mb  = full_base + slot * 8;
                uint32_t dst = smem_base + (uint32_t)slot * CHUNK_BYTES;
                long pr   = (long)blockIdx.x + (long)(cn >> 3) * GRID_P;
                long tile = pr * 2 + (cn & 1);
                int y = (int)(tile * TILE_M);       // may be OOB for phantom tile
                int x = ((cn >> 1) & 3) * 32;
                asm volatile("mbarrier.arrive.expect_tx.shared.b64 _, [%0], %1;"
                             :: "r"(mb), "n"(CHUNK_BYTES) : "memory");
                asm volatile("cp.async.bulk.tensor.2d.shared::cta.global.tile.mbarrier::complete_tx::bytes "
                             "[%0], [%1, {%2, %3}], [%4];"
                             :: "r"(dst), "l"(tmap_ptr), "r"(x), "r"(y), "r"(mb) : "memory");
            }
        }
        return;
    }

    // ======================= consumer warps ======================
    const int r0 = warp * 16;
    const int rowA = r0 + g;                           // rows rowA, rowA+8
    const uint32_t xm = (uint32_t)((g & 7) << 4);      // SW128 XOR mask (rows differ by 8)
    const char* smem_c = (const char*)smem;
    const uint32_t* blane = Bf + lane * 20;

    float acc0[8][4], acc1[8][4];                      // tile0 / tile1 of the pair
    const int S = C >> 1;                              // pair-q steps

    for (int s = 0; s < S; s++) {
        const int c0 = s * 2, c1 = c0 + 1;
        const int slot0 = c0 & (NSTAGES - 1);
        const int slot1 = c1 & (NSTAGES - 1);
        mbar_wait(full_base + slot0 * 8, (c0 >> 3) & 1);
        mbar_wait(full_base + slot1 * 8, (c1 >> 3) & 1);

        const char* sb0 = smem_c + slot0 * CHUNK_BYTES;
        const char* sb1 = smem_c + slot1 * CHUNK_BYTES;
        const int q = s & 3;

        if (q == 0) {
            #pragma unroll
            for (int nt = 0; nt < 8; nt++) {
                acc0[nt][0] = 0.f; acc0[nt][1] = 0.f; acc0[nt][2] = 0.f; acc0[nt][3] = 0.f;
                acc1[nt][0] = 0.f; acc1[nt][1] = 0.f; acc1[nt][2] = 0.f; acc1[nt][3] = 0.f;
            }
        }

        #pragma unroll
        for (int kkl = 0; kkl < 4; kkl++) {
            const uint32_t* bp = blane + (q * 4 + kkl) * 640;
            uint4 b01 = *(const uint4*)(bp);
            uint4 b23 = *(const uint4*)(bp + 4);
            uint4 b45 = *(const uint4*)(bp + 8);
            uint4 b67 = *(const uint4*)(bp + 12);

            uint32_t cb = (uint32_t)((kkl * 8 + tq) * 4);
            const char* p0 = sb0 + rowA * 128;
            uint32_t a0 = f2tf32(*(const float*)(p0 + (cb ^ xm)));
            uint32_t a2 = f2tf32(*(const float*)(p0 + ((cb + 16) ^ xm)));
            uint32_t a1 = f2tf32(*(const float*)(p0 + 1024 + (cb ^ xm)));
            uint32_t a3 = f2tf32(*(const float*)(p0 + 1024 + ((cb + 16) ^ xm)));
            MMA_TF32(acc0[0], a0, a1, a2, a3, b01.x, b01.y);
            MMA_TF32(acc0[1], a0, a1, a2, a3, b01.z, b01.w);
            MMA_TF32(acc0[2], a0, a1, a2, a3, b23.x, b23.y);
            MMA_TF32(acc0[3], a0, a1, a2, a3, b23.z, b23.w);
            MMA_TF32(acc0[4], a0, a1, a2, a3, b45.x, b45.y);
            MMA_TF32(acc0[5], a0, a1, a2, a3, b45.z, b45.w);
            MMA_TF32(acc0[6], a0, a1, a2, a3, b67.x, b67.y);
            MMA_TF32(acc0[7], a0, a1, a2, a3, b67.z, b67.w);

            const char* p1 = sb1 + rowA * 128;
            uint32_t c0r = f2tf32(*(const float*)(p1 + (cb ^ xm)));
            uint32_t c2r = f2tf32(*(const float*)(p1 + ((cb + 16) ^ xm)));
            uint32_t c1r = f2tf32(*(const float*)(p1 + 1024 + (cb ^ xm)));
            uint32_t c3r = f2tf32(*(const float*)(p1 + 1024 + ((cb + 16) ^ xm)));
            MMA_TF32(acc1[0], c0r, c1r, c2r, c3r, b01.x, b01.y);
            MMA_TF32(acc1[1], c0r, c1r, c2r, c3r, b01.z, b01.w);
            MMA_TF32(acc1[2], c0r, c1r, c2r, c3r, b23.x, b23.y);
            MMA_TF32(acc1[3], c0r, c1r, c2r, c3r, b23.z, b23.w);
            MMA_TF32(acc1[4], c0r, c1r, c2r, c3r, b45.x, b45.y);
            MMA_TF32(acc1[5], c0r, c1r, c2r, c3r, b45.z, b45.w);
            MMA_TF32(acc1[6], c0r, c1r, c2r, c3r, b67.x, b67.y);
            MMA_TF32(acc1[7], c0r, c1r, c2r, c3r, b67.z, b67.w);
        }

        // signal both slots consumed (one arrive per consumer warp each)
        if (lane == 0) {
            mbar_arrive(empty_base + slot0 * 8);
            mbar_arrive(empty_base + slot1 * 8);
        }

        if (q == 3) {
            long pr = (long)blockIdx.x + (long)(s >> 2) * GRID_P;
            #pragma unroll
            for (int t = 0; t < 2; t++) {
                float (*acc)[4] = t ? acc1 : acc0;
                float sA = 0.f, sB = 0.f;
                #pragma unroll
                for (int nt = 0; nt < 8; nt++) {
                    int col0 = nt * 8 + tq * 2;
                    int col1 = col0 + 1;
                    float w0 = w2s[col0], w1v = w2s[col1];
                    float bb0 = b1s[col0], bb1 = b1s[col1];
                    sA += silu(acc[nt][0] + bb0) * w0;
                    sA += silu(acc[nt][1] + bb1) * w1v;
                    sB += silu(acc[nt][2] + bb0) * w0;
                    sB += silu(acc[nt][3] + bb1) * w1v;
                }
                #pragma unroll
                for (int o = 1; o <= 2; o <<= 1) {
                    sA += __shfl_xor_sync(0xFFFFFFFFu, sA, o);
                    sB += __shfl_xor_sync(0xFFFFFFFFu, sB, o);
                }
                if (tq == 0) {
                    long rA = (pr * 2 + t) * TILE_M + r0 + g;
                    if (rA     < n_atoms) g_atom_out[rA]     = sA + b2v;
                    if (rA + 8 < n_atoms) g_atom_out[rA + 8] = sB + b2v;
                }
            }
        }
    }
}

// ---------------------------------------------------------------------------
// Kernel 2: segment boundary detection over sorted batch (coalesced).
// ---------------------------------------------------------------------------
__global__ void bounds_kernel(const int* __restrict__ batch, int n_atoms, int n_mol)
{
    int i = blockIdx.x * blockDim.x + threadIdx.x;
    if (i >= n_atoms) return;
    int b = batch[i];
    if (i == 0) {
        for (int m = 0; m <= b; m++) g_start[m] = 0;
    } else {
        int p = batch[i - 1];
        for (int m = p + 1; m <= b; m++) g_start[m] = i;
    }
    if (i == n_atoms - 1) {
        for (int m = b + 1; m <= n_mol; m++) g_start[m] = n_atoms;
    }
}

// ---------------------------------------------------------------------------
// Kernel 3: warp per molecule — coalesced segment sum, correction, writes.
// ---------------------------------------------------------------------------
__global__ void seg_out_kernel(const float* __restrict__ charge,
                               float* __restrict__ out, int n_mol)
{
    int w    = (blockIdx.x * blockDim.x + threadIdx.x) >> 5;
    int lane = threadIdx.x & 31;
    if (w >= n_mol) return;
    int s = g_start[w], e = g_start[w + 1];
    int cnt = e - s;
    if (cnt <= 0) return;
    float sum = 0.f;
    for (int i = s + lane; i < e; i += 32) sum += g_atom_out[i];
    #pragma unroll
    for (int o = 16; o; o >>= 1) sum += __shfl_xor_sync(0xFFFFFFFFu, sum, o);
    float corr = (charge[w] - sum) / (float)cnt;
    for (int i = s + lane; i < e; i += 32) out[i] = g_atom_out[i] + corr;
}

// ---------------------------------------------------------------------------
typedef CUresult (CUDAAPI *encode_fn_t)(
    CUtensorMap*, CUtensorMapDataType, cuuint32_t, void*,
    const cuuint64_t*, const cuuint64_t*, const cuuint32_t*, const cuuint32_t*,
    CUtensorMapInterleave, CUtensorMapSwizzle, CUtensorMapL2promotion,
    CUtensorMapFloatOOBfill);

extern "C" void kernel_launch(void* const* d_in, const int* in_sizes, int n_in,
                              void* d_out, int out_size)
{
    const float* x      = (const float*)d_in[0];
    const int*   batch  = (const int*)  d_in[1];
    const float* charge = (const float*)d_in[2];
    const float* W1     = (const float*)d_in[3];
    const float* b1     = (const float*)d_in[4];
    const float* W2     = (const float*)d_in[5];
    const float* b2     = (const float*)d_in[6];
    float* out = (float*)d_out;

    const int n_atoms = in_sizes[0] / K_DIM;
    const int n_mol   = in_sizes[2];
    const int ntiles  = (n_atoms + TILE_M - 1) / TILE_M;
    const int npairs  = (ntiles + 1) / 2;

    static encode_fn_t encode = nullptr;
    if (!encode) {
        void* fn = nullptr;
        cudaDriverEntryPointQueryResult qr;
        cudaGetDriverEntryPoint("cuTensorMapEncodeTiled", &fn,
                                cudaEnableDefault, &qr);
        encode = (encode_fn_t)fn;
    }

    CUtensorMap tmap;
    cuuint64_t dims[2]    = {(cuuint64_t)K_DIM, (cuuint64_t)n_atoms};
    cuuint64_t strides[1] = {(cuuint64_t)K_DIM * 4};
    cuuint32_t box[2]     = {32u, 128u};
    cuuint32_t es[2]      = {1u, 1u};
    encode(&tmap, CU_TENSOR_MAP_DATA_TYPE_FLOAT32, 2, (void*)x,
           dims, strides, box, es,
           CU_TENSOR_MAP_INTERLEAVE_NONE, CU_TENSOR_MAP_SWIZZLE_128B,
           CU_TENSOR_MAP_L2_PROMOTION_L2_128B, CU_TENSOR_MAP_FLOAT_OOB_FILL_NONE);

    const int smem_bytes = SMEM_FLOATS * 4;
    cudaFuncSetAttribute(mlp_kernel, cudaFuncAttributeMaxDynamicSharedMemorySize,
                         smem_bytes);

    mlp_kernel<<<GRID_P, NTHREADS, smem_bytes>>>(tmap, W1, b1, W2, b2, n_atoms, npairs);
    bounds_kernel<<<(n_atoms + 255) / 256, 256>>>(batch, n_atoms, n_mol);
    seg_out_kernel<<<(n_mol * 32 + 255) / 256, 256>>>(charge, out, n_mol);
}

// round 15
// speedup vs baseline: 1.1501x; 1.0496x over previous
#include <cuda_runtime.h>
#include <cuda.h>
#include <cstdint>

#define N_ATOMS_MAX 2000000
#define N_MOL_MAX   50000

#define K_DIM   128
#define N_DIM   64
#define TILE_M  128
#define GRID_P  304          // 2 blocks per SM on 152-SM GB300
#define NSTAGES 4
#define CHUNK_BYTES  16384   // 128 rows x 32 f32 (128B/row, SW128)
#define NTHREADS 256         // 8 consumer warps (16 rows each), RR TMA issue

// smem float offsets
#define BF_OFF     16384     // after 4 x 4096-float X stages
#define B1_OFF     26624     // Bf = 10240 u32 (40 KB, stride-20 conflict-free)
#define W2_OFF     26688
#define FULL_OFF   26752     // 4 x u64
#define EMPTY_OFF  26760     // 4 x u64
#define SMEM_FLOATS 26768

// scratch (no device allocation allowed)
__device__ float g_atom_out[N_ATOMS_MAX];
__device__ int   g_start[N_MOL_MAX + 1];

__device__ __forceinline__ uint32_t f2tf32(float f) {
    uint32_t u;
    asm("cvt.rna.tf32.f32 %0, %1;" : "=r"(u) : "f"(f));
    return u;
}
__device__ __forceinline__ float silu(float v) {
    return __fdividef(v, 1.0f + __expf(-v));
}
__device__ __forceinline__ void mbar_init(uint32_t mb, uint32_t cnt) {
    asm volatile("mbarrier.init.shared.b64 [%0], %1;" :: "r"(mb), "r"(cnt) : "memory");
}
__device__ __forceinline__ void mbar_wait(uint32_t mb, uint32_t phase) {
    asm volatile(
        "{\n\t.reg .pred P;\n"
        "W%=:\n\t"
        "mbarrier.try_wait.parity.acquire.cta.shared::cta.b64 P, [%0], %1, 0x989680;\n\t"
        "@P bra D%=;\n\t"
        "bra W%=;\n"
        "D%=:\n\t}"
        :: "r"(mb), "r"(phase) : "memory");
}
__device__ __forceinline__ void mbar_arrive(uint32_t mb) {
    asm volatile("mbarrier.arrive.shared.b64 _, [%0];" :: "r"(mb) : "memory");
}
#define MMA_TF32(C, A0, A1, A2, A3, B0, B1)                                   \
    asm("mma.sync.aligned.m16n8k8.row.col.f32.tf32.tf32.f32 "                 \
        "{%0,%1,%2,%3}, {%4,%5,%6,%7}, {%8,%9}, {%0,%1,%2,%3};"               \
        : "+f"(C[0]), "+f"(C[1]), "+f"(C[2]), "+f"(C[3])                      \
        : "r"(A0), "r"(A1), "r"(A2), "r"(A3), "r"(B0), "r"(B1))

// ---------------------------------------------------------------------------
// Kernel 1: persistent per-atom MLP, TMA-fed 4-deep ring, mbarrier-only sync.
// 8 consumer warps x 16 rows (max latency-hiding parallelism); TMA issue
// distributed round-robin: chunk cn issued by lane 0 of warp cn&7.
// ---------------------------------------------------------------------------
__global__ __launch_bounds__(NTHREADS, 2)
void mlp_kernel(const __grid_constant__ CUtensorMap tmap,
                const float* __restrict__ W1,
                const float* __restrict__ b1,
                const float* __restrict__ W2,
                const float* __restrict__ b2,
                int n_atoms, int ntiles)
{
    extern __shared__ __align__(1024) float smem[];
    uint32_t* Bf  = (uint32_t*)(smem + BF_OFF);
    float*    b1s = smem + B1_OFF;
    float*    w2s = smem + W2_OFF;
    const uint32_t smem_base  = (uint32_t)__cvta_generic_to_shared(smem);
    const uint32_t full_base  = smem_base + FULL_OFF * 4u;
    const uint32_t empty_base = smem_base + EMPTY_OFF * 4u;
    const uint64_t tmap_ptr   = (uint64_t)&tmap;

    const int tid  = threadIdx.x;
    const int lane = tid & 31, warp = tid >> 5;
    const int g = lane >> 2, tq = lane & 3;

    // ---- stage W1 once: tf32, fragment-major, lane stride 20 (conflict-free) ----
    #pragma unroll
    for (int i = 0; i < 32; i++) {
        int e = tid + NTHREADS * i;          // e = k*64 + n (coalesced)
        int k = e >> 6, n = e & 63;
        uint32_t v = f2tf32(W1[e]);
        int gg = n & 7, nt = n >> 3, kk = k >> 3, kb = k & 7;
        int tq2 = kb & 3, j = nt * 2 + (kb >> 2);
        Bf[kk * 640 + (gg * 4 + tq2) * 20 + j] = v;
    }
    if (tid < N_DIM) { b1s[tid] = b1[tid]; w2s[tid] = W2[tid]; }
    const float b2v = b2[0];

    const int nloc = (blockIdx.x < ntiles) ? (ntiles - blockIdx.x + GRID_P - 1) / GRID_P : 0;
    const int C = nloc * 4;                  // chunks: (tile, quarter-K)

    if (tid == 0) {
        #pragma unroll
        for (int s = 0; s < NSTAGES; s++) {
            mbar_init(full_base  + s * 8, 1);
            mbar_init(empty_base + s * 8, 8);
        }
        asm volatile("fence.proxy.async.shared::cta;" ::: "memory");
    }
    __syncthreads();
    if (C <= 0) return;

    // producer: issue one 16KB TMA chunk into slot cn%4 (caller = lane0 of warp cn&7)
    auto issue = [&](int cn) {
        int slot = cn & (NSTAGES - 1);
        if (cn >= NSTAGES)                                  // wait slot consumed
            mbar_wait(empty_base + slot * 8, ((cn >> 2) + 1) & 1);
        uint32_t mb  = full_base + slot * 8;
        uint32_t dst = smem_base + (uint32_t)slot * CHUNK_BYTES;
        long tile = (long)blockIdx.x + (long)(cn >> 2) * GRID_P;
        int y = (int)(tile * TILE_M);
        int x = (cn & 3) * 32;
        asm volatile("mbarrier.arrive.expect_tx.shared.b64 _, [%0], %1;"
                     :: "r"(mb), "n"(CHUNK_BYTES) : "memory");
        asm volatile("cp.async.bulk.tensor.2d.shared::cta.global.tile.mbarrier::complete_tx::bytes "
                     "[%0], [%1, {%2, %3}], [%4];"
                     :: "r"(dst), "l"(tmap_ptr), "r"(x), "r"(y), "r"(mb) : "memory");
    };

    // prefetch: chunk cn issued by its owner warp (cn & 7), lane 0
    {
        int pre = (C < NSTAGES - 1) ? C : NSTAGES - 1;
        for (int cn = 0; cn < pre; cn++)
            if (warp == (cn & 7) && lane == 0) issue(cn);
    }

    // per-thread A addressing (constant across chunks)
    const int r0 = warp * 16;
    const int rowA = r0 + g;                           // rows rowA, rowA+8
    const uint32_t xm = (uint32_t)((g & 7) << 4);      // SW128 XOR mask (rows differ by 8)
    const char* smem_c = (const char*)smem;
    const uint32_t* blane = Bf + lane * 20;

    float acc[8][4];

    for (int c = 0; c < C; c++) {
        {
            int cn = c + NSTAGES - 1;
            if (cn < C && warp == (cn & 7) && lane == 0) issue(cn);
        }
        const int slot = c & (NSTAGES - 1);
        mbar_wait(full_base + slot * 8, (c >> 2) & 1);

        const char* slotb = smem_c + slot * CHUNK_BYTES;
        const int q = c & 3;                 // quarter-K index

        if (q == 0) {
            #pragma unroll
            for (int nt = 0; nt < 8; nt++) {
                acc[nt][0] = 0.f; acc[nt][1] = 0.f;
                acc[nt][2] = 0.f; acc[nt][3] = 0.f;
            }
        }

        #pragma unroll
        for (int kkl = 0; kkl < 4; kkl++) {
            uint32_t cb = (uint32_t)((kkl * 8 + tq) * 4);
            const char* pr = slotb + rowA * 128;
            uint32_t a0 = f2tf32(*(const float*)(pr + (cb ^ xm)));
            uint32_t a2 = f2tf32(*(const float*)(pr + ((cb + 16) ^ xm)));
            uint32_t a1 = f2tf32(*(const float*)(pr + 1024 + (cb ^ xm)));
            uint32_t a3 = f2tf32(*(const float*)(pr + 1024 + ((cb + 16) ^ xm)));
            const uint32_t* bp = blane + (q * 4 + kkl) * 640;
            uint4 b01 = *(const uint4*)(bp);
            uint4 b23 = *(const uint4*)(bp + 4);
            uint4 b45 = *(const uint4*)(bp + 8);
            uint4 b67 = *(const uint4*)(bp + 12);
            MMA_TF32(acc[0], a0, a1, a2, a3, b01.x, b01.y);
            MMA_TF32(acc[1], a0, a1, a2, a3, b01.z, b01.w);
            MMA_TF32(acc[2], a0, a1, a2, a3, b23.x, b23.y);
            MMA_TF32(acc[3], a0, a1, a2, a3, b23.z, b23.w);
            MMA_TF32(acc[4], a0, a1, a2, a3, b45.x, b45.y);
            MMA_TF32(acc[5], a0, a1, a2, a3, b45.z, b45.w);
            MMA_TF32(acc[6], a0, a1, a2, a3, b67.x, b67.y);
            MMA_TF32(acc[7], a0, a1, a2, a3, b67.z, b67.w);
        }

        // signal slot consumed (one arrive per warp; data already in regs)
        if (lane == 0) mbar_arrive(empty_base + slot * 8);

        if (q == 3) {
            // epilogue: +b1, silu, dot W2, reduce over tq lanes, store 2 rows
            float sA = 0.f, sB = 0.f;
            #pragma unroll
            for (int nt = 0; nt < 8; nt++) {
                int col0 = nt * 8 + tq * 2;
                int col1 = col0 + 1;
                float w0 = w2s[col0], w1v = w2s[col1];
                float bb0 = b1s[col0], bb1 = b1s[col1];
                sA += silu(acc[nt][0] + bb0) * w0;
                sA += silu(acc[nt][1] + bb1) * w1v;
                sB += silu(acc[nt][2] + bb0) * w0;
                sB += silu(acc[nt][3] + bb1) * w1v;
            }
            #pragma unroll
            for (int o = 1; o <= 2; o <<= 1) {
                sA += __shfl_xor_sync(0xFFFFFFFFu, sA, o);
                sB += __shfl_xor_sync(0xFFFFFFFFu, sB, o);
            }
            if (tq == 0) {
                long tile = (long)blockIdx.x + (long)(c >> 2) * GRID_P;
                long rA = tile * TILE_M + r0 + g;
                if (rA     < n_atoms) g_atom_out[rA]     = sA + b2v;
                if (rA + 8 < n_atoms) g_atom_out[rA + 8] = sB + b2v;
            }
        }
    }
}

// ---------------------------------------------------------------------------
// Kernel 2: segment boundary detection over sorted batch (coalesced).
// ---------------------------------------------------------------------------
__global__ void bounds_kernel(const int* __restrict__ batch, int n_atoms, int n_mol)
{
    int i = blockIdx.x * blockDim.x + threadIdx.x;
    if (i >= n_atoms) return;
    int b = batch[i];
    if (i == 0) {
        for (int m = 0; m <= b; m++) g_start[m] = 0;
    } else {
        int p = batch[i - 1];
        for (int m = p + 1; m <= b; m++) g_start[m] = i;
    }
    if (i == n_atoms - 1) {
        for (int m = b + 1; m <= n_mol; m++) g_start[m] = n_atoms;
    }
}

// ---------------------------------------------------------------------------
// Kernel 3: warp per molecule — coalesced segment sum, correction, writes.
// ---------------------------------------------------------------------------
__global__ void seg_out_kernel(const float* __restrict__ charge,
                               float* __restrict__ out, int n_mol)
{
    int w    = (blockIdx.x * blockDim.x + threadIdx.x) >> 5;
    int lane = threadIdx.x & 31;
    if (w >= n_mol) return;
    int s = g_start[w], e = g_start[w + 1];
    int cnt = e - s;
    if (cnt <= 0) return;
    float sum = 0.f;
    for (int i = s + lane; i < e; i += 32) sum += g_atom_out[i];
    #pragma unroll
    for (int o = 16; o; o >>= 1) sum += __shfl_xor_sync(0xFFFFFFFFu, sum, o);
    float corr = (charge[w] - sum) / (float)cnt;
    for (int i = s + lane; i < e; i += 32) out[i] = g_atom_out[i] + corr;
}

// ---------------------------------------------------------------------------
typedef CUresult (CUDAAPI *encode_fn_t)(
    CUtensorMap*, CUtensorMapDataType, cuuint32_t, void*,
    const cuuint64_t*, const cuuint64_t*, const cuuint32_t*, const cuuint32_t*,
    CUtensorMapInterleave, CUtensorMapSwizzle, CUtensorMapL2promotion,
    CUtensorMapFloatOOBfill);

extern "C" void kernel_launch(void* const* d_in, const int* in_sizes, int n_in,
                              void* d_out, int out_size)
{
    const float* x      = (const float*)d_in[0];
    const int*   batch  = (const int*)  d_in[1];
    const float* charge = (const float*)d_in[2];
    const float* W1     = (const float*)d_in[3];
    const float* b1     = (const float*)d_in[4];
    const float* W2     = (const float*)d_in[5];
    const float* b2     = (const float*)d_in[6];
    float* out = (float*)d_out;

    const int n_atoms = in_sizes[0] / K_DIM;
    const int n_mol   = in_sizes[2];
    const int ntiles  = (n_atoms + TILE_M - 1) / TILE_M;

    static encode_fn_t encode = nullptr;
    if (!encode) {
        void* fn = nullptr;
        cudaDriverEntryPointQueryResult qr;
        cudaGetDriverEntryPoint("cuTensorMapEncodeTiled", &fn,
                                cudaEnableDefault, &qr);
        encode = (encode_fn_t)fn;
    }

    CUtensorMap tmap;
    cuuint64_t dims[2]    = {(cuuint64_t)K_DIM, (cuuint64_t)n_atoms};
    cuuint64_t strides[1] = {(cuuint64_t)K_DIM * 4};
    cuuint32_t box[2]     = {32u, 128u};
    cuuint32_t es[2]      = {1u, 1u};
    encode(&tmap, CU_TENSOR_MAP_DATA_TYPE_FLOAT32, 2, (void*)x,
           dims, strides, box, es,
           CU_TENSOR_MAP_INTERLEAVE_NONE, CU_TENSOR_MAP_SWIZZLE_128B,
           CU_TENSOR_MAP_L2_PROMOTION_L2_128B, CU_TENSOR_MAP_FLOAT_OOB_FILL_NONE);

    const int smem_bytes = SMEM_FLOATS * 4;
    cudaFuncSetAttribute(mlp_kernel, cudaFuncAttributeMaxDynamicSharedMemorySize,
                         smem_bytes);

    mlp_kernel<<<GRID_P, NTHREADS, smem_bytes>>>(tmap, W1, b1, W2, b2, n_atoms, ntiles);
    bounds_kernel<<<(n_atoms + 255) / 256, 256>>>(batch, n_atoms, n_mol);
    seg_out_kernel<<<(n_mol * 32 + 255) / 256, 256>>>(charge, out, n_mol);
}